// round 15
// baseline (speedup 1.0000x reference)
#include <cuda_runtime.h>
#include <cstdint>

// RNN: h_{t+1} = tanh(x_t * W_ih + b_ih + W_hh @ h_t + b_hh), out = fc_w . h_T + fc_b
// B=4096, T=512, I=1, H=64.
// One 64-thread CTA per batch element. Thread t owns W_hh row t (64 floats in
// registers, packed as 32 f32x2 pairs). Per step: 16 LDS.128 of the shared h
// vector (broadcast), 32 fma.rn.f32x2, tanh, 1 store, 1 barrier (double buffer).

#define Hdim 64
#define Tlen 512

__device__ __forceinline__ void fma2(unsigned long long& acc,
                                     unsigned long long a,
                                     unsigned long long b) {
    asm("fma.rn.f32x2 %0, %1, %2, %0;" : "+l"(acc) : "l"(a), "l"(b));
}

__global__ void __launch_bounds__(Hdim, 16)
rnn_kernel(const float* __restrict__ x,
           const float* __restrict__ W_ih,
           const float* __restrict__ W_hh,
           const float* __restrict__ b_ih,
           const float* __restrict__ b_hh,
           const float* __restrict__ fc_w,
           const float* __restrict__ fc_b,
           float* __restrict__ out) {
    __shared__ __align__(16) float sx[Tlen];
    __shared__ __align__(16) float sh[2][Hdim];
    __shared__ float sred[2];

    const int t = threadIdx.x;          // 0..63  (output row index)
    const int b = blockIdx.x;           // batch element

    // ---- stage x[b, 0..511] into smem (coalesced float4) ----
    {
        const float4* xrow = reinterpret_cast<const float4*>(x + (size_t)b * Tlen);
        reinterpret_cast<float4*>(sx)[t]          = xrow[t];
        reinterpret_cast<float4*>(sx)[t + Hdim]   = xrow[t + Hdim];
    }

    // ---- preload W_hh row t into registers as 32 packed f32x2 pairs ----
    unsigned long long w[Hdim / 2];
    {
        const ulonglong2* wr = reinterpret_cast<const ulonglong2*>(W_hh + t * Hdim);
        #pragma unroll
        for (int i = 0; i < Hdim / 4; i++) {
            ulonglong2 v = wr[i];
            w[2 * i]     = v.x;
            w[2 * i + 1] = v.y;
        }
    }

    const float wi = W_ih[t];                 // I == 1
    const float cb = b_ih[t] + b_hh[t];

    sh[0][t] = 0.0f;                          // h0 = 0
    __syncthreads();

    float hval = 0.0f;

    #pragma unroll 2
    for (int s = 0; s < Tlen; s++) {
        const int cur = s & 1;

        // dot(W_hh[t,:], h) with packed f32x2 FMAs
        unsigned long long acc0 = 0ull, acc1 = 0ull;
        const ulonglong2* hrow = reinterpret_cast<const ulonglong2*>(&sh[cur][0]);
        #pragma unroll
        for (int i = 0; i < Hdim / 4; i++) {
            ulonglong2 v = hrow[i];           // LDS.128, broadcast across CTA
            fma2(acc0, w[2 * i],     v.x);
            fma2(acc1, w[2 * i + 1], v.y);
        }
        unsigned long long acc;
        asm("add.rn.f32x2 %0, %1, %2;" : "=l"(acc) : "l"(acc0), "l"(acc1));
        float lo, hi;
        asm("mov.b64 {%0, %1}, %2;" : "=f"(lo), "=f"(hi) : "l"(acc));

        const float pre = fmaf(sx[s], wi, cb) + (lo + hi);
        hval = tanhf(pre);

        sh[cur ^ 1][t] = hval;                // write to other buffer
        __syncthreads();                      // one barrier per step
    }

    // ---- final linear: out[b] = sum_t hval_t * fc_w[t] + fc_b ----
    float p = hval * fc_w[t];
    #pragma unroll
    for (int o = 16; o > 0; o >>= 1)
        p += __shfl_xor_sync(0xffffffffu, p, o);
    if ((t & 31) == 0) sred[t >> 5] = p;
    __syncthreads();
    if (t == 0) out[b] = sred[0] + sred[1] + fc_b[0];
}

extern "C" void kernel_launch(void* const* d_in, const int* in_sizes, int n_in,
                              void* d_out, int out_size) {
    const float* x    = (const float*)d_in[0];
    const float* W_ih = (const float*)d_in[1];
    const float* W_hh = (const float*)d_in[2];
    const float* b_ih = (const float*)d_in[3];
    const float* b_hh = (const float*)d_in[4];
    const float* fc_w = (const float*)d_in[5];
    const float* fc_b = (const float*)d_in[6];
    float* out = (float*)d_out;

    const int B = in_sizes[0] / Tlen;   // x has B*T*1 elements
    rnn_kernel<<<B, Hdim>>>(x, W_ih, W_hh, b_ih, b_hh, fc_w, fc_b, out);
}